// round 1
// baseline (speedup 1.0000x reference)
#include <cuda_runtime.h>
#include <math.h>

#define NB 16
#define NC 64
#define NT 128
#define ND 256
#define NH 8
#define NKD 32
#define NTOPK 8

// ---------------- device scratch (no allocations allowed) ----------------
__device__ float g_hmean[NB * NC * ND];
__device__ float g_adaptive[NB * NC * NC];
__device__ unsigned long long g_maskcol[NB * NC];  // bit i set => edge i -> j
__device__ float g_vsrc[NH * ND];
__device__ float g_vdst[NH * ND];

// ---------------- kernel A: temporal mean ----------------
__global__ void k_hmean(const float* __restrict__ x) {
    int bc = blockIdx.x;     // b*C + c
    int d = threadIdx.x;     // 256 threads
    const float* p = x + (size_t)bc * NT * ND + d;
    float s = 0.f;
#pragma unroll 8
    for (int t = 0; t < NT; ++t) s += p[(size_t)t * ND];
    g_hmean[bc * ND + d] = s * (1.0f / NT);
}

// ---------------- kernel D: v_src[h,d] = sum_f att[h,f] * gat_lin[h*D+f, d] ----------------
__global__ void k_vsd(const float* __restrict__ gat_lin,
                      const float* __restrict__ att_src,
                      const float* __restrict__ att_dst) {
    int h = blockIdx.x & 7;
    int isdst = blockIdx.x >> 3;
    int d = threadIdx.x;  // 256
    const float* att = isdst ? att_dst : att_src;
    float acc = 0.f;
#pragma unroll 4
    for (int f = 0; f < ND; ++f)
        acc += att[h * ND + f] * gat_lin[((size_t)(h * ND + f)) * ND + d];
    (isdst ? g_vdst : g_vsrc)[h * ND + d] = acc;
}

// ---------------- kernel B: q/k, sim, tanh -> delta_a (output) + adaptive; init self loops ----------------
__global__ void k_adj(const float* __restrict__ static_adj,
                      const float* __restrict__ w_q,
                      const float* __restrict__ w_k,
                      float* __restrict__ delta_out) {
    __shared__ float q_s[NC * NKD];
    __shared__ float k_s[NC * NKD];
    int b = blockIdx.x;
    int tid = threadIdx.x;  // 256
    if (tid < NC) g_maskcol[b * NC + tid] = 1ull << tid;  // self loop

    for (int task = tid; task < 2 * NC * NKD; task += 256) {
        int which = task >= NC * NKD;
        int t2 = task - which * NC * NKD;
        int c = t2 / NKD, kd = t2 % NKD;
        const float* w = which ? w_k : w_q;
        const float* hrow = g_hmean + (size_t)(b * NC + c) * ND;
        const float* wrow = w + (size_t)kd * ND;
        float acc = 0.f;
#pragma unroll 4
        for (int d = 0; d < ND; ++d) acc += hrow[d] * wrow[d];
        (which ? k_s : q_s)[c * NKD + kd] = acc;
    }
    __syncthreads();
    const float inv = 0.17677669529663687f;  // 1/sqrt(32)
    for (int task = tid; task < NC * NC; task += 256) {
        int i = task / NC, j = task % NC;
        float acc = 0.f;
#pragma unroll
        for (int kd = 0; kd < NKD; ++kd) acc += q_s[i * NKD + kd] * k_s[j * NKD + kd];
        float delta = tanhf(acc * inv);
        delta_out[b * NC * NC + task] = delta;
        g_adaptive[b * NC * NC + task] = static_adj[task] + delta;
    }
}

// ---------------- kernel C: per-row top-8 of |adaptive| -> column bitmasks ----------------
__global__ void k_topk() {
    int b = blockIdx.x / NC, i = blockIdx.x % NC;
    int lane = threadIdx.x;  // 32
    const float* row = g_adaptive + (size_t)(b * NC + i) * NC;
    float v0 = fabsf(row[lane]);
    float v1 = fabsf(row[lane + 32]);
    for (int s = 0; s < NTOPK; ++s) {
        float bv; int bj;
        if (v0 >= v1) { bv = v0; bj = lane; } else { bv = v1; bj = lane + 32; }
#pragma unroll
        for (int off = 16; off > 0; off >>= 1) {
            float ov = __shfl_xor_sync(0xffffffffu, bv, off);
            int   oj = __shfl_xor_sync(0xffffffffu, bj, off);
            if (ov > bv || (ov == bv && oj < bj)) { bv = ov; bj = oj; }
        }
        if (lane == 0) atomicOr(&g_maskcol[b * NC + bj], 1ull << i);
        if (bj == lane)      v0 = -1.0f;
        if (bj == lane + 32) v1 = -1.0f;
    }
}

// ---------------- kernel F: main GAT per (b,t) ----------------
#define XS_STRIDE 264
#define GS_STRIDE 33
#define AS_STRIDE 65
#define FTHREADS 512
#define SMEM_FLOATS (NC * XS_STRIDE * 2 + NC * AS_STRIDE + ND * GS_STRIDE + 2 * NH * ND + 2 * NH * NC)
#define SMEM_BYTES (SMEM_FLOATS * 4)

__global__ __launch_bounds__(FTHREADS, 1)
void k_main(const float* __restrict__ x,
            const float* __restrict__ gat_lin,
            const float* __restrict__ gat_bias,
            float* __restrict__ out) {
    extern __shared__ float sm[];
    float* x_s     = sm;                       // [64][264]
    float* z_s     = x_s + NC * XS_STRIDE;     // [64][264]
    float* alpha_s = z_s + NC * XS_STRIDE;     // [64 i][65] (col j)
    float* g_s     = alpha_s + NC * AS_STRIDE; // [256 f][33]
    float* v_s     = g_s + ND * GS_STRIDE;     // [2][8][256]
    float* as_s    = v_s + 2 * NH * ND;        // [8 h][64 i]
    float* ad_s    = as_s + NH * NC;           // [8 h][64 j]

    int bt = blockIdx.x;
    int b = bt >> 7;
    int t = bt & 127;
    int tid = threadIdx.x;

    // load x_bt [64 x 256]
    for (int idx = tid; idx < NC * ND; idx += FTHREADS) {
        int i = idx >> 8, d = idx & 255;
        x_s[i * XS_STRIDE + d] = x[(((size_t)b * NC + i) * NT + t) * ND + d];
    }
    for (int idx = tid; idx < 2 * NH * ND; idx += FTHREADS)
        v_s[idx] = (idx < NH * ND) ? g_vsrc[idx] : g_vdst[idx - NH * ND];
    __syncthreads();

    // a_src[i,h], a_dst[i,h]
    for (int task = tid; task < NC * 2 * NH; task += FTHREADS) {
        int i = task >> 4;
        int hh = task & 15;
        int h = hh & 7, isd = hh >> 3;
        const float* v = v_s + (isd * NH + h) * ND;
        const float* xr = x_s + i * XS_STRIDE;
        float acc = 0.f;
#pragma unroll 8
        for (int d = 0; d < ND; ++d) acc += xr[d] * v[d];
        (isd ? ad_s : as_s)[h * NC + i] = acc;
    }
    __syncthreads();

    const int tf = tid & 31;  // f = tf + 32*s (s<8) / d = tf + 32*s
    const int tj = tid >> 5;  // j = tj + 16*r (r<4), warp-uniform
    float out_acc[4][8];
#pragma unroll
    for (int r = 0; r < 4; ++r)
#pragma unroll
        for (int s = 0; s < 8; ++s) out_acc[r][s] = 0.f;

    const float NEGINF = __int_as_float(0xff800000);

    for (int h = 0; h < NH; ++h) {
        // ---- alpha[i][j] = masked softmax over i ----
        {
            int w = tid >> 5, lane = tid & 31;
#pragma unroll
            for (int jj = 0; jj < 4; ++jj) {
                int j = w * 4 + jj;
                unsigned long long m = g_maskcol[b * NC + j];
                float adj = ad_s[h * NC + j];
                int i0 = lane, i1 = lane + 32;
                float e0 = as_s[h * NC + i0] + adj;
                float e1 = as_s[h * NC + i1] + adj;
                e0 = e0 > 0.f ? e0 : 0.2f * e0;   // leaky_relu(0.2)
                e1 = e1 > 0.f ? e1 : 0.2f * e1;
                bool m0 = (m >> i0) & 1ull;
                bool m1 = (m >> i1) & 1ull;
                float mx = fmaxf(m0 ? e0 : NEGINF, m1 ? e1 : NEGINF);
#pragma unroll
                for (int off = 16; off > 0; off >>= 1)
                    mx = fmaxf(mx, __shfl_xor_sync(0xffffffffu, mx, off));
                float p0 = m0 ? expf(e0 - mx) : 0.f;
                float p1 = m1 ? expf(e1 - mx) : 0.f;
                float ssum = p0 + p1;
#pragma unroll
                for (int off = 16; off > 0; off >>= 1)
                    ssum += __shfl_xor_sync(0xffffffffu, ssum, off);
                float invs = 1.0f / ssum;
                alpha_s[i0 * AS_STRIDE + j] = p0 * invs;
                alpha_s[i1 * AS_STRIDE + j] = p1 * invs;
            }
        }
        __syncthreads();

        // ---- z[j][d] = sum_i alpha[i][j] * x[i][d] ----
        {
            float z_acc[4][8];
#pragma unroll
            for (int r = 0; r < 4; ++r)
#pragma unroll
                for (int s = 0; s < 8; ++s) z_acc[r][s] = 0.f;
#pragma unroll 2
            for (int i = 0; i < NC; ++i) {
                float a[4];
#pragma unroll
                for (int r = 0; r < 4; ++r) a[r] = alpha_s[i * AS_STRIDE + tj + 16 * r];
                float xr[8];
#pragma unroll
                for (int s = 0; s < 8; ++s) xr[s] = x_s[i * XS_STRIDE + tf + 32 * s];
#pragma unroll
                for (int r = 0; r < 4; ++r)
#pragma unroll
                    for (int s = 0; s < 8; ++s) z_acc[r][s] += a[r] * xr[s];
            }
#pragma unroll
            for (int r = 0; r < 4; ++r)
#pragma unroll
                for (int s = 0; s < 8; ++s)
                    z_s[(tj + 16 * r) * XS_STRIDE + tf + 32 * s] = z_acc[r][s];
        }
        __syncthreads();

        // ---- out[j][f] += sum_d z[j][d] * G_h[f][d] ----
        const float* G = gat_lin + (size_t)h * ND * ND;
        for (int dt = 0; dt < ND; dt += 32) {
            for (int idx = tid; idx < ND * 32; idx += FTHREADS) {
                int f = idx >> 5, k = idx & 31;
                g_s[f * GS_STRIDE + k] = G[(size_t)f * ND + dt + k];
            }
            __syncthreads();
#pragma unroll 4
            for (int k = 0; k < 32; ++k) {
                float zr[4];
#pragma unroll
                for (int r = 0; r < 4; ++r) zr[r] = z_s[(tj + 16 * r) * XS_STRIDE + dt + k];
                float gr[8];
#pragma unroll
                for (int s = 0; s < 8; ++s) gr[s] = g_s[(tf + 32 * s) * GS_STRIDE + k];
#pragma unroll
                for (int r = 0; r < 4; ++r)
#pragma unroll
                    for (int s = 0; s < 8; ++s) out_acc[r][s] += zr[r] * gr[s];
            }
            __syncthreads();
        }
    }

    // epilogue: mean over heads + bias, write x_updated[b,j,t,f]
#pragma unroll
    for (int r = 0; r < 4; ++r) {
        int j = tj + 16 * r;
#pragma unroll
        for (int s = 0; s < 8; ++s) {
            int f = tf + 32 * s;
            float val = out_acc[r][s] * (1.0f / NH) + __ldg(gat_bias + f);
            out[(((size_t)b * NC + j) * NT + t) * ND + f] = val;
        }
    }
}

// ---------------- launch ----------------
extern "C" void kernel_launch(void* const* d_in, const int* in_sizes, int n_in,
                              void* d_out, int out_size) {
    const float* x          = (const float*)d_in[0];
    const float* static_adj = (const float*)d_in[1];
    const float* w_q        = (const float*)d_in[2];
    const float* w_k        = (const float*)d_in[3];
    const float* gat_lin    = (const float*)d_in[4];
    const float* att_src    = (const float*)d_in[5];
    const float* att_dst    = (const float*)d_in[6];
    const float* gat_bias   = (const float*)d_in[7];

    float* out = (float*)d_out;
    float* delta_out = out + (size_t)NB * NC * NT * ND;  // delta_a after x_updated

    cudaFuncSetAttribute(k_main, cudaFuncAttributeMaxDynamicSharedMemorySize, SMEM_BYTES);

    k_hmean<<<NB * NC, 256>>>(x);
    k_vsd<<<16, 256>>>(gat_lin, att_src, att_dst);
    k_adj<<<NB, 256>>>(static_adj, w_q, w_k, delta_out);
    k_topk<<<NB * NC, 32>>>();
    k_main<<<NB * NT, FTHREADS, SMEM_BYTES>>>(x, gat_lin, gat_bias, out);
}